// round 3
// baseline (speedup 1.0000x reference)
#include <cuda_runtime.h>
#include <cuda_bf16.h>
#include <math.h>

// Problem constants (shapes are fixed by the dataset).
#define NN      50000
#define EEDGES  800000
#define ETOT    (EEDGES + NN)       // with self loops
#define IN_DIM  128
#define H1N     4
#define C1N     64
#define D1      (H1N * C1N)          // 256
#define D2      64
#define EPS_BN  1e-5f
#define NEG_SLOPE 0.2f

// -------------------- scratch (static __device__, no allocs) ----------------
__device__ float    g_h1  [NN * D1];       // x@W1, later reused as BN1/ELU output (layer2 input)
__device__ float    g_o1  [NN * D1];       // GAT1 aggregation output
__device__ float    g_as1 [NN * H1N];
__device__ float    g_ad1 [NN * H1N];
__device__ unsigned g_m1  [NN * H1N];
__device__ float    g_den1[NN * H1N];
__device__ float    g_e1  [(size_t)ETOT * H1N];
__device__ float    g_h2  [NN * D2];
__device__ float    g_o2  [NN * D2];
__device__ float    g_as2 [NN];
__device__ float    g_ad2 [NN];
__device__ unsigned g_m2  [NN];
__device__ float    g_den2[NN];
__device__ float    g_e2  [ETOT];
__device__ float    g_proj[NN * IN_DIM];
__device__ double   g_sum [256];
__device__ double   g_sq  [256];
__device__ float    g_mean[256];
__device__ float    g_rstd[256];

// -------------------- helpers ----------------------------------------------
__device__ __forceinline__ unsigned f_ord(float f) {
    unsigned u = __float_as_uint(f);
    return (u & 0x80000000u) ? ~u : (u | 0x80000000u);
}
__device__ __forceinline__ float ord_f(unsigned u) {
    return __uint_as_float((u & 0x80000000u) ? (u & 0x7fffffffu) : ~u);
}
__device__ __forceinline__ void edge_sd(const int* __restrict__ ei, int e, int E,
                                        int& s, int& d) {
    if (e < E) { s = ei[e]; d = ei[E + e]; }
    else       { s = e - E; d = e - E; }     // self loop
}

// -------------------- GEMM: C[M,Nc] = A[M,K] @ B[K,Nc] ----------------------
#define BM 64
#define BN 64
#define BKK 16
__global__ __launch_bounds__(256) void gemm_kernel(
    const float* __restrict__ A, const float* __restrict__ B,
    float* __restrict__ C, int M, int Nc, int K)
{
    __shared__ float As[BKK][BM + 1];
    __shared__ float Bs[BKK][BN];
    int tid = threadIdx.x;
    int tx = tid & 15, ty = tid >> 4;
    int row0 = blockIdx.y * BM, col0 = blockIdx.x * BN;
    float acc[4][4] = {};
    for (int k0 = 0; k0 < K; k0 += BKK) {
        {   // load A tile (64 rows x 16 k), transposed into As[k][m]
            int r = tid >> 2, c4 = (tid & 3) * 4;
            float4 v = make_float4(0, 0, 0, 0);
            if (row0 + r < M)
                v = *(const float4*)(A + (size_t)(row0 + r) * K + k0 + c4);
            As[c4 + 0][r] = v.x; As[c4 + 1][r] = v.y;
            As[c4 + 2][r] = v.z; As[c4 + 3][r] = v.w;
        }
        {   // load B tile (16 k x 64 cols)
            int r = tid >> 4, c4 = (tid & 15) * 4;
            *(float4*)&Bs[r][c4] =
                *(const float4*)(B + (size_t)(k0 + r) * Nc + col0 + c4);
        }
        __syncthreads();
        #pragma unroll
        for (int kk = 0; kk < BKK; kk++) {
            float a[4], b[4];
            #pragma unroll
            for (int i = 0; i < 4; i++) a[i] = As[kk][ty * 4 + i];
            #pragma unroll
            for (int j = 0; j < 4; j++) b[j] = Bs[kk][tx * 4 + j];
            #pragma unroll
            for (int i = 0; i < 4; i++)
                #pragma unroll
                for (int j = 0; j < 4; j++) acc[i][j] += a[i] * b[j];
        }
        __syncthreads();
    }
    #pragma unroll
    for (int i = 0; i < 4; i++) {
        int r = row0 + ty * 4 + i;
        if (r < M) {
            #pragma unroll
            for (int j = 0; j < 4; j++)
                C[(size_t)r * Nc + col0 + tx * 4 + j] = acc[i][j];
        }
    }
}

// -------------------- attention coefficients: [N,H] dot over C --------------
__global__ void alpha_kernel(const float* __restrict__ h,
                             const float* __restrict__ asrc,
                             const float* __restrict__ adst,
                             float* __restrict__ out_s, float* __restrict__ out_d,
                             int N, int H, int C)
{
    int w = (blockIdx.x * blockDim.x + threadIdx.x) >> 5;
    int lane = threadIdx.x & 31;
    if (w >= N * H) return;
    int n = w / H, hh = w - n * H;
    const float* hp = h + (size_t)n * H * C + hh * C;
    float s = 0.f, d = 0.f;
    for (int c = lane; c < C; c += 32) {
        float v = hp[c];
        s += v * asrc[hh * C + c];
        d += v * adst[hh * C + c];
    }
    #pragma unroll
    for (int o = 16; o; o >>= 1) {
        s += __shfl_down_sync(0xffffffffu, s, o);
        d += __shfl_down_sync(0xffffffffu, d, o);
    }
    if (lane == 0) { out_s[w] = s; out_d[w] = d; }
}

// -------------------- edge pass 1: logits + segment max ---------------------
__global__ void logit_kernel(const int* __restrict__ ei,
                             const float* __restrict__ as_, const float* __restrict__ ad_,
                             float* __restrict__ eo, unsigned* __restrict__ m,
                             int Etot, int E, int H)
{
    int e = blockIdx.x * blockDim.x + threadIdx.x;
    if (e >= Etot) return;
    int s, d; edge_sd(ei, e, E, s, d);
    for (int h = 0; h < H; h++) {
        float v = as_[s * H + h] + ad_[d * H + h];
        v = v > 0.f ? v : NEG_SLOPE * v;
        eo[(size_t)e * H + h] = v;
        atomicMax(&m[d * H + h], f_ord(v));
    }
}

// -------------------- edge pass 2: exp + segment sum ------------------------
__global__ void exp_kernel(const int* __restrict__ ei,
                           const unsigned* __restrict__ m,
                           float* __restrict__ eo, float* __restrict__ den,
                           int Etot, int E, int H)
{
    int e = blockIdx.x * blockDim.x + threadIdx.x;
    if (e >= Etot) return;
    int s, d; edge_sd(ei, e, E, s, d);
    for (int h = 0; h < H; h++) {
        float mx = ord_f(m[d * H + h]);
        float ex = expf(eo[(size_t)e * H + h] - mx);
        eo[(size_t)e * H + h] = ex;
        atomicAdd(&den[d * H + h], ex);
    }
}

// -------------------- edge pass 3: weighted scatter -------------------------
// C threads per edge (C=64 here), loop over heads.
__global__ void scatter_kernel(const int* __restrict__ ei,
                               const float* __restrict__ ex, const float* __restrict__ den,
                               const float* __restrict__ h, float* __restrict__ out,
                               int Etot, int E, int H, int C)
{
    long long t = (long long)blockIdx.x * blockDim.x + threadIdx.x;
    int e = (int)(t / C);
    int c = (int)(t - (long long)e * C);
    if (e >= Etot) return;
    int s, d; edge_sd(ei, e, E, s, d);
    for (int hh = 0; hh < H; hh++) {
        float a = ex[(size_t)e * H + hh] / (den[d * H + hh] + 1e-16f);
        atomicAdd(&out[(size_t)d * H * C + hh * C + c],
                  a * h[(size_t)s * H * C + hh * C + c]);
    }
}

// -------------------- batchnorm stats (fp64 accumulation) -------------------
__global__ void bn_stats_kernel(const float* __restrict__ x,
                                double* __restrict__ sum, double* __restrict__ sq,
                                int N, int C)
{
    int c = threadIdx.x;        // blockDim.x == C
    double s = 0.0, q = 0.0;
    for (int r = blockIdx.x; r < N; r += gridDim.x) {
        double v = (double)x[(size_t)r * C + c];
        s += v; q += v * v;
    }
    atomicAdd(&sum[c], s);
    atomicAdd(&sq[c], q);
}

__global__ void bn_final_kernel(const double* __restrict__ sum, const double* __restrict__ sq,
                                float* __restrict__ mean, float* __restrict__ rstd,
                                int N, int C)
{
    int c = blockIdx.x * blockDim.x + threadIdx.x;
    if (c >= C) return;
    double mu = sum[c] / N;
    double var = sq[c] / N - mu * mu;
    mean[c] = (float)mu;
    rstd[c] = (float)(1.0 / sqrt(var + (double)EPS_BN));
}

__global__ void bn_apply_kernel(const float* __restrict__ x, float* __restrict__ y,
                                const float* __restrict__ mean, const float* __restrict__ rstd,
                                const float* __restrict__ g, const float* __restrict__ be,
                                int N, int C, int do_elu)
{
    int i = blockIdx.x * blockDim.x + threadIdx.x;
    if (i >= N * C) return;
    int c = i % C;
    float v = (x[i] - mean[c]) * rstd[c] * g[c] + be[c];
    if (do_elu) v = v > 0.f ? v : expf(v) - 1.f;
    y[i] = v;
}

// -------------------- launch -----------------------------------------------
extern "C" void kernel_launch(void* const* d_in, const int* in_sizes, int n_in,
                              void* d_out, int out_size)
{
    const float* x   = (const float*)d_in[0];
    const int*   ei  = (const int*)  d_in[1];
    const float* W1  = (const float*)d_in[2];
    const float* a1s = (const float*)d_in[3];
    const float* a1d = (const float*)d_in[4];
    // d_in[5] = b1 : followed by BN -> channel-shift invariant -> skipped
    const float* W2  = (const float*)d_in[6];
    const float* a2s = (const float*)d_in[7];
    const float* a2d = (const float*)d_in[8];
    // d_in[9] = b2 : skipped (BN invariance)
    const float* Wp  = (const float*)d_in[10];
    // d_in[11] = bp : skipped (BN invariance)
    const float* g1  = (const float*)d_in[12];
    const float* be1 = (const float*)d_in[13];
    const float* g2  = (const float*)d_in[14];
    const float* be2 = (const float*)d_in[15];
    const float* g3  = (const float*)d_in[16];
    const float* be3 = (const float*)d_in[17];
    float* out = (float*)d_out;

    const int N = in_sizes[0] / IN_DIM;       // 50000
    const int E = in_sizes[1] / 2;            // 800000
    const int Etot = E + N;

    float *h1, *o1, *as1, *ad1, *den1, *e1;
    float *h2, *o2, *as2, *ad2, *den2, *e2, *proj, *meanp, *rstdp;
    unsigned *m1, *m2;
    double *sump, *sqp;
    cudaGetSymbolAddress((void**)&h1,   g_h1);
    cudaGetSymbolAddress((void**)&o1,   g_o1);
    cudaGetSymbolAddress((void**)&as1,  g_as1);
    cudaGetSymbolAddress((void**)&ad1,  g_ad1);
    cudaGetSymbolAddress((void**)&m1,   g_m1);
    cudaGetSymbolAddress((void**)&den1, g_den1);
    cudaGetSymbolAddress((void**)&e1,   g_e1);
    cudaGetSymbolAddress((void**)&h2,   g_h2);
    cudaGetSymbolAddress((void**)&o2,   g_o2);
    cudaGetSymbolAddress((void**)&as2,  g_as2);
    cudaGetSymbolAddress((void**)&ad2,  g_ad2);
    cudaGetSymbolAddress((void**)&m2,   g_m2);
    cudaGetSymbolAddress((void**)&den2, g_den2);
    cudaGetSymbolAddress((void**)&e2,   g_e2);
    cudaGetSymbolAddress((void**)&proj, g_proj);
    cudaGetSymbolAddress((void**)&sump, g_sum);
    cudaGetSymbolAddress((void**)&sqp,  g_sq);
    cudaGetSymbolAddress((void**)&meanp, g_mean);
    cudaGetSymbolAddress((void**)&rstdp, g_rstd);

    cudaStream_t st = 0;

    // zero-init accumulators (0 is identity for our ordered-uint max too,
    // since every node has a self loop writing a real logit >= 0x007FFFFF)
    cudaMemsetAsync(o1,   0, (size_t)N * D1 * sizeof(float), st);
    cudaMemsetAsync(den1, 0, (size_t)N * H1N * sizeof(float), st);
    cudaMemsetAsync(m1,   0, (size_t)N * H1N * sizeof(unsigned), st);
    cudaMemsetAsync(o2,   0, (size_t)N * D2 * sizeof(float), st);
    cudaMemsetAsync(den2, 0, (size_t)N * sizeof(float), st);
    cudaMemsetAsync(m2,   0, (size_t)N * sizeof(unsigned), st);

    // ---------------- layer 1: GATConv(128 -> 4x64, concat) ----------------
    {
        dim3 grid(D1 / BN, (N + BM - 1) / BM);
        gemm_kernel<<<grid, 256, 0, st>>>(x, W1, h1, N, D1, IN_DIM);
    }
    {
        int warps = N * H1N;
        alpha_kernel<<<(warps * 32 + 255) / 256, 256, 0, st>>>(h1, a1s, a1d, as1, ad1, N, H1N, C1N);
    }
    logit_kernel<<<(Etot + 255) / 256, 256, 0, st>>>(ei, as1, ad1, e1, m1, Etot, E, H1N);
    exp_kernel  <<<(Etot + 255) / 256, 256, 0, st>>>(ei, m1, e1, den1, Etot, E, H1N);
    {
        long long threads = (long long)Etot * C1N;
        scatter_kernel<<<(unsigned)((threads + 255) / 256), 256, 0, st>>>(
            ei, e1, den1, h1, o1, Etot, E, H1N, C1N);
    }
    // BN1 + ELU -> h1 (reused as layer-2 input)
    cudaMemsetAsync(sump, 0, D1 * sizeof(double), st);
    cudaMemsetAsync(sqp,  0, D1 * sizeof(double), st);
    bn_stats_kernel<<<512, D1, 0, st>>>(o1, sump, sqp, N, D1);
    bn_final_kernel<<<1, D1, 0, st>>>(sump, sqp, meanp, rstdp, N, D1);
    bn_apply_kernel<<<((size_t)N * D1 + 255) / 256, 256, 0, st>>>(
        o1, h1, meanp, rstdp, g1, be1, N, D1, 1);

    // ---------------- layer 2: GATConv(256 -> 64, H=1) ---------------------
    {
        dim3 grid(D2 / BN, (N + BM - 1) / BM);
        gemm_kernel<<<grid, 256, 0, st>>>(h1, W2, h2, N, D2, D1);
    }
    alpha_kernel<<<(N * 32 + 255) / 256, 256, 0, st>>>(h2, a2s, a2d, as2, ad2, N, 1, D2);
    logit_kernel<<<(Etot + 255) / 256, 256, 0, st>>>(ei, as2, ad2, e2, m2, Etot, E, 1);
    exp_kernel  <<<(Etot + 255) / 256, 256, 0, st>>>(ei, m2, e2, den2, Etot, E, 1);
    {
        long long threads = (long long)Etot * D2;
        scatter_kernel<<<(unsigned)((threads + 255) / 256), 256, 0, st>>>(
            ei, e2, den2, h2, o2, Etot, E, 1, D2);
    }
    // BN2 + ELU -> h2 (reused as projection input)
    cudaMemsetAsync(sump, 0, D2 * sizeof(double), st);
    cudaMemsetAsync(sqp,  0, D2 * sizeof(double), st);
    bn_stats_kernel<<<512, D2, 0, st>>>(o2, sump, sqp, N, D2);
    bn_final_kernel<<<1, D2, 0, st>>>(sump, sqp, meanp, rstdp, N, D2);
    bn_apply_kernel<<<((size_t)N * D2 + 255) / 256, 256, 0, st>>>(
        o2, h2, meanp, rstdp, g2, be2, N, D2, 1);

    // ---------------- projection 64 -> 128 + BN3 ---------------------------
    {
        dim3 grid(IN_DIM / BN, (N + BM - 1) / BM);
        gemm_kernel<<<grid, 256, 0, st>>>(h2, Wp, proj, N, IN_DIM, D2);
    }
    cudaMemsetAsync(sump, 0, IN_DIM * sizeof(double), st);
    cudaMemsetAsync(sqp,  0, IN_DIM * sizeof(double), st);
    bn_stats_kernel<<<512, IN_DIM, 0, st>>>(proj, sump, sqp, N, IN_DIM);
    bn_final_kernel<<<1, IN_DIM, 0, st>>>(sump, sqp, meanp, rstdp, N, IN_DIM);
    bn_apply_kernel<<<((size_t)N * IN_DIM + 255) / 256, 256, 0, st>>>(
        proj, out, meanp, rstdp, g3, be3, N, IN_DIM, 0);
}

// round 6
// speedup vs baseline: 1.3866x; 1.3866x over previous
#include <cuda_runtime.h>
#include <cuda_bf16.h>
#include <math.h>

// Problem constants (shapes fixed by the dataset).
#define NN      50000
#define EEDGES  800000
#define IN_DIM  128
#define H1N     4
#define C1N     64
#define D1      (H1N * C1N)          // 256
#define D2      64
#define EPS_BN  1e-5f
#define NEG_SLOPE 0.2f
#define NEG_BIG  (-1e30f)

// -------------------- scratch (static __device__, no allocs) ----------------
__device__ float    g_h1  [NN * D1];       // x@W1, then BN1/ELU output (layer2 input)
__device__ float    g_o1  [NN * D1];       // GAT1 aggregation output
__device__ float    g_as1 [NN * H1N];
__device__ float    g_ad1 [NN * H1N];
__device__ float    g_h2  [NN * D2];
__device__ float    g_o2  [NN * D2];
__device__ float    g_as2 [NN];
__device__ float    g_ad2 [NN];
__device__ float    g_proj[NN * IN_DIM];
__device__ int      g_deg [NN];
__device__ int      g_rowptr[NN + 1];
__device__ int      g_cursor[NN];
__device__ int      g_srcs[EEDGES];
__device__ double   g_sum [256];
__device__ double   g_sq  [256];
__device__ float    g_mean[256];
__device__ float    g_rstd[256];

// -------------------- GEMM: C[M,Nc] = A[M,K] @ B[K,Nc] ----------------------
#define BM 64
#define BN 64
#define BKK 16
__global__ __launch_bounds__(256) void gemm_kernel(
    const float* __restrict__ A, const float* __restrict__ B,
    float* __restrict__ C, int M, int Nc, int K)
{
    __shared__ float As[BKK][BM + 1];
    __shared__ float Bs[BKK][BN];
    int tid = threadIdx.x;
    int tx = tid & 15, ty = tid >> 4;
    int row0 = blockIdx.y * BM, col0 = blockIdx.x * BN;
    float acc[4][4] = {};
    for (int k0 = 0; k0 < K; k0 += BKK) {
        {   // load A tile (64 rows x 16 k), transposed into As[k][m]
            int r = tid >> 2, c4 = (tid & 3) * 4;
            float4 v = make_float4(0, 0, 0, 0);
            if (row0 + r < M)
                v = *(const float4*)(A + (size_t)(row0 + r) * K + k0 + c4);
            As[c4 + 0][r] = v.x; As[c4 + 1][r] = v.y;
            As[c4 + 2][r] = v.z; As[c4 + 3][r] = v.w;
        }
        {   // load B tile (16 k x 64 cols)
            int r = tid >> 4, c4 = (tid & 15) * 4;
            *(float4*)&Bs[r][c4] =
                *(const float4*)(B + (size_t)(k0 + r) * Nc + col0 + c4);
        }
        __syncthreads();
        #pragma unroll
        for (int kk = 0; kk < BKK; kk++) {
            float a[4], b[4];
            #pragma unroll
            for (int i = 0; i < 4; i++) a[i] = As[kk][ty * 4 + i];
            #pragma unroll
            for (int j = 0; j < 4; j++) b[j] = Bs[kk][tx * 4 + j];
            #pragma unroll
            for (int i = 0; i < 4; i++)
                #pragma unroll
                for (int j = 0; j < 4; j++) acc[i][j] += a[i] * b[j];
        }
        __syncthreads();
    }
    #pragma unroll
    for (int i = 0; i < 4; i++) {
        int r = row0 + ty * 4 + i;
        if (r < M) {
            #pragma unroll
            for (int j = 0; j < 4; j++)
                C[(size_t)r * Nc + col0 + tx * 4 + j] = acc[i][j];
        }
    }
}

// -------------------- attention coefficients: [N,H] dot over C --------------
__global__ void alpha_kernel(const float* __restrict__ h,
                             const float* __restrict__ asrc,
                             const float* __restrict__ adst,
                             float* __restrict__ out_s, float* __restrict__ out_d,
                             int N, int H, int C)
{
    int w = (blockIdx.x * blockDim.x + threadIdx.x) >> 5;
    int lane = threadIdx.x & 31;
    if (w >= N * H) return;
    int n = w / H, hh = w - n * H;
    const float* hp = h + (size_t)n * H * C + hh * C;
    float s = 0.f, d = 0.f;
    for (int c = lane; c < C; c += 32) {
        float v = hp[c];
        s += v * asrc[hh * C + c];
        d += v * adst[hh * C + c];
    }
    #pragma unroll
    for (int o = 16; o; o >>= 1) {
        s += __shfl_down_sync(0xffffffffu, s, o);
        d += __shfl_down_sync(0xffffffffu, d, o);
    }
    if (lane == 0) { out_s[w] = s; out_d[w] = d; }
}

// -------------------- CSR build (dst-sorted incoming edge lists) ------------
__global__ void degree_kernel(const int* __restrict__ ei, int* __restrict__ deg, int E)
{
    int e = blockIdx.x * blockDim.x + threadIdx.x;
    if (e < E) atomicAdd(&deg[ei[E + e]], 1);
}

__global__ __launch_bounds__(1024) void scan_kernel(
    const int* __restrict__ deg, int* __restrict__ rowptr,
    int* __restrict__ cursor, int N)
{
    __shared__ int part[1024];
    int tid = threadIdx.x;
    int chunk = (N + 1023) / 1024;
    int b = tid * chunk, e = min(b + chunk, N);
    int s = 0;
    for (int i = b; i < e; i++) s += deg[i];
    part[tid] = s;
    __syncthreads();
    for (int o = 1; o < 1024; o <<= 1) {
        int v = (tid >= o) ? part[tid - o] : 0;
        __syncthreads();
        part[tid] += v;
        __syncthreads();
    }
    int run = tid ? part[tid - 1] : 0;
    for (int i = b; i < e; i++) {
        rowptr[i] = run; cursor[i] = run;
        run += deg[i];
    }
    if (tid == 1023) rowptr[N] = part[1023];
}

__global__ void fill_kernel(const int* __restrict__ ei, int* __restrict__ cursor,
                            int* __restrict__ srcs, int E)
{
    int e = blockIdx.x * blockDim.x + threadIdx.x;
    if (e >= E) return;
    int d = ei[E + e];
    int p = atomicAdd(&cursor[d], 1);
    srcs[p] = ei[e];
}

// -------------------- fused GAT aggregation (gather, no atomics) ------------
// One warp per (node, head). Online softmax over incoming edges + self loop,
// then weighted accumulation of h[src] (2 channels/lane, C == 64).
// NOTE: lane-local max starts at NEG_BIG (finite!) — a -INF start makes the
// butterfly combine compute expf(-inf - -inf) = NaN for empty-lane pairs.
__global__ void gat_agg_kernel(const int* __restrict__ srcs,
                               const int* __restrict__ rowptr,
                               const float* __restrict__ as_,
                               const float* __restrict__ ad_,
                               const float* __restrict__ h,
                               float* __restrict__ out,
                               int N, int H, int C)
{
    int gw = (blockIdx.x * blockDim.x + threadIdx.x) >> 5;
    int lane = threadIdx.x & 31;
    if (gw >= N * H) return;
    int n = gw / H, hd = gw - n * H;
    int beg = rowptr[n], end = rowptr[n + 1];
    float ad = ad_[n * H + hd];
    float as_self = as_[n * H + hd];

    // pass 1: per-lane online (max, sumexp), self loop on lane 0
    float m = NEG_BIG, ssum = 0.f;
    if (lane == 0) {
        float v = as_self + ad;
        v = v > 0.f ? v : NEG_SLOPE * v;
        m = v; ssum = 1.f;
    }
    for (int e = beg + lane; e < end; e += 32) {
        float v = as_[srcs[e] * H + hd] + ad;
        v = v > 0.f ? v : NEG_SLOPE * v;
        float mn = fmaxf(m, v);
        ssum = ssum * expf(m - mn) + expf(v - mn);
        m = mn;
    }
    // warp combine (all values finite -> no NaN)
    #pragma unroll
    for (int o = 16; o; o >>= 1) {
        float m2 = __shfl_xor_sync(0xffffffffu, m, o);
        float s2 = __shfl_xor_sync(0xffffffffu, ssum, o);
        float mn = fmaxf(m, m2);
        ssum = ssum * expf(m - mn) + s2 * expf(m2 - mn);
        m = mn;
    }
    float inv = 1.f / (ssum + 1e-16f);

    // pass 2: weighted accumulation, lanes own channels (lane, lane+32)
    float acc0 = 0.f, acc1 = 0.f;
    for (int e = beg; e < end; e++) {
        int s = srcs[e];
        float v = as_[s * H + hd] + ad;              // broadcast load
        v = v > 0.f ? v : NEG_SLOPE * v;
        float a = expf(v - m) * inv;
        const float* hp = h + ((size_t)s * H + hd) * C;
        acc0 += a * hp[lane];
        acc1 += a * hp[lane + 32];
    }
    {   // self loop
        float v = as_self + ad;
        v = v > 0.f ? v : NEG_SLOPE * v;
        float a = expf(v - m) * inv;
        const float* hp = h + ((size_t)n * H + hd) * C;
        acc0 += a * hp[lane];
        acc1 += a * hp[lane + 32];
    }
    float* op = out + ((size_t)n * H + hd) * C;
    op[lane]      = acc0;
    op[lane + 32] = acc1;
}

// -------------------- batchnorm stats (fp32 partials, fp64 combine) ---------
__global__ void bn_stats_kernel(const float* __restrict__ x,
                                double* __restrict__ sum, double* __restrict__ sq,
                                int N, int C)
{
    int c = threadIdx.x;        // blockDim.x == C
    float s = 0.f, q = 0.f;
    for (int r = blockIdx.x; r < N; r += gridDim.x) {
        float v = x[(size_t)r * C + c];
        s += v; q += v * v;
    }
    atomicAdd(&sum[c], (double)s);
    atomicAdd(&sq[c], (double)q);
}

__global__ void bn_final_kernel(const double* __restrict__ sum, const double* __restrict__ sq,
                                float* __restrict__ mean, float* __restrict__ rstd,
                                int N, int C)
{
    int c = blockIdx.x * blockDim.x + threadIdx.x;
    if (c >= C) return;
    double mu = sum[c] / N;
    double var = sq[c] / N - mu * mu;
    mean[c] = (float)mu;
    rstd[c] = (float)(1.0 / sqrt(var + (double)EPS_BN));
}

__global__ void bn_apply_kernel(const float* __restrict__ x, float* __restrict__ y,
                                const float* __restrict__ mean, const float* __restrict__ rstd,
                                const float* __restrict__ g, const float* __restrict__ be,
                                int N, int C, int do_elu)
{
    int i4 = blockIdx.x * blockDim.x + threadIdx.x;      // float4 index
    size_t total4 = ((size_t)N * C) >> 2;
    if ((size_t)i4 >= total4) return;
    int c0 = (i4 << 2) % C;
    float4 v = ((const float4*)x)[i4];
    float r[4] = {v.x, v.y, v.z, v.w};
    #pragma unroll
    for (int j = 0; j < 4; j++) {
        int c = c0 + j;
        float t = (r[j] - mean[c]) * rstd[c] * g[c] + be[c];
        if (do_elu) t = t > 0.f ? t : expf(t) - 1.f;
        r[j] = t;
    }
    ((float4*)y)[i4] = make_float4(r[0], r[1], r[2], r[3]);
}

// -------------------- launch -----------------------------------------------
extern "C" void kernel_launch(void* const* d_in, const int* in_sizes, int n_in,
                              void* d_out, int out_size)
{
    const float* x   = (const float*)d_in[0];
    const int*   ei  = (const int*)  d_in[1];
    const float* W1  = (const float*)d_in[2];
    const float* a1s = (const float*)d_in[3];
    const float* a1d = (const float*)d_in[4];
    // d_in[5] = b1 : followed by BN -> channel-shift invariant -> skipped
    const float* W2  = (const float*)d_in[6];
    const float* a2s = (const float*)d_in[7];
    const float* a2d = (const float*)d_in[8];
    // d_in[9] = b2 : skipped (BN invariance)
    const float* Wp  = (const float*)d_in[10];
    // d_in[11] = bp : skipped (BN invariance)
    const float* g1  = (const float*)d_in[12];
    const float* be1 = (const float*)d_in[13];
    const float* g2  = (const float*)d_in[14];
    const float* be2 = (const float*)d_in[15];
    const float* g3  = (const float*)d_in[16];
    const float* be3 = (const float*)d_in[17];
    float* out = (float*)d_out;

    const int N = in_sizes[0] / IN_DIM;       // 50000
    const int E = in_sizes[1] / 2;            // 800000

    float *h1, *o1, *as1, *ad1;
    float *h2, *o2, *as2, *ad2, *proj, *meanp, *rstdp;
    int *deg, *rowptr, *cursor, *srcs;
    double *sump, *sqp;
    cudaGetSymbolAddress((void**)&h1,   g_h1);
    cudaGetSymbolAddress((void**)&o1,   g_o1);
    cudaGetSymbolAddress((void**)&as1,  g_as1);
    cudaGetSymbolAddress((void**)&ad1,  g_ad1);
    cudaGetSymbolAddress((void**)&h2,   g_h2);
    cudaGetSymbolAddress((void**)&o2,   g_o2);
    cudaGetSymbolAddress((void**)&as2,  g_as2);
    cudaGetSymbolAddress((void**)&ad2,  g_ad2);
    cudaGetSymbolAddress((void**)&proj, g_proj);
    cudaGetSymbolAddress((void**)&deg,    g_deg);
    cudaGetSymbolAddress((void**)&rowptr, g_rowptr);
    cudaGetSymbolAddress((void**)&cursor, g_cursor);
    cudaGetSymbolAddress((void**)&srcs,   g_srcs);
    cudaGetSymbolAddress((void**)&sump, g_sum);
    cudaGetSymbolAddress((void**)&sqp,  g_sq);
    cudaGetSymbolAddress((void**)&meanp, g_mean);
    cudaGetSymbolAddress((void**)&rstdp, g_rstd);

    cudaStream_t st = 0;

    // ---------------- CSR build (shared by both layers) ---------------------
    cudaMemsetAsync(deg, 0, (size_t)N * sizeof(int), st);
    degree_kernel<<<(E + 255) / 256, 256, 0, st>>>(ei, deg, E);
    scan_kernel<<<1, 1024, 0, st>>>(deg, rowptr, cursor, N);
    fill_kernel<<<(E + 255) / 256, 256, 0, st>>>(ei, cursor, srcs, E);

    // ---------------- layer 1: GATConv(128 -> 4x64, concat) ----------------
    {
        dim3 grid(D1 / BN, (N + BM - 1) / BM);
        gemm_kernel<<<grid, 256, 0, st>>>(x, W1, h1, N, D1, IN_DIM);
    }
    alpha_kernel<<<(N * H1N * 32 + 255) / 256, 256, 0, st>>>(h1, a1s, a1d, as1, ad1, N, H1N, C1N);
    gat_agg_kernel<<<(N * H1N * 32 + 255) / 256, 256, 0, st>>>(
        srcs, rowptr, as1, ad1, h1, o1, N, H1N, C1N);

    // BN1 + ELU -> h1 (reused as layer-2 input)
    cudaMemsetAsync(sump, 0, D1 * sizeof(double), st);
    cudaMemsetAsync(sqp,  0, D1 * sizeof(double), st);
    bn_stats_kernel<<<512, D1, 0, st>>>(o1, sump, sqp, N, D1);
    bn_final_kernel<<<1, D1, 0, st>>>(sump, sqp, meanp, rstdp, N, D1);
    bn_apply_kernel<<<(((size_t)N * D1 / 4) + 255) / 256, 256, 0, st>>>(
        o1, h1, meanp, rstdp, g1, be1, N, D1, 1);

    // ---------------- layer 2: GATConv(256 -> 64, H=1) ---------------------
    {
        dim3 grid(D2 / BN, (N + BM - 1) / BM);
        gemm_kernel<<<grid, 256, 0, st>>>(h1, W2, h2, N, D2, D1);
    }
    alpha_kernel<<<(N * 32 + 255) / 256, 256, 0, st>>>(h2, a2s, a2d, as2, ad2, N, 1, D2);
    gat_agg_kernel<<<(N * 32 + 255) / 256, 256, 0, st>>>(
        srcs, rowptr, as2, ad2, h2, o2, N, 1, D2);

    // BN2 + ELU -> h2 (reused as projection input)
    cudaMemsetAsync(sump, 0, D2 * sizeof(double), st);
    cudaMemsetAsync(sqp,  0, D2 * sizeof(double), st);
    bn_stats_kernel<<<512, D2, 0, st>>>(o2, sump, sqp, N, D2);
    bn_final_kernel<<<1, D2, 0, st>>>(sump, sqp, meanp, rstdp, N, D2);
    bn_apply_kernel<<<(((size_t)N * D2 / 4) + 255) / 256, 256, 0, st>>>(
        o2, h2, meanp, rstdp, g2, be2, N, D2, 1);

    // ---------------- projection 64 -> 128 + BN3 ---------------------------
    {
        dim3 grid(IN_DIM / BN, (N + BM - 1) / BM);
        gemm_kernel<<<grid, 256, 0, st>>>(h2, Wp, proj, N, IN_DIM, D2);
    }
    cudaMemsetAsync(sump, 0, IN_DIM * sizeof(double), st);
    cudaMemsetAsync(sqp,  0, IN_DIM * sizeof(double), st);
    bn_stats_kernel<<<512, IN_DIM, 0, st>>>(proj, sump, sqp, N, IN_DIM);
    bn_final_kernel<<<1, IN_DIM, 0, st>>>(sump, sqp, meanp, rstdp, N, IN_DIM);
    bn_apply_kernel<<<(((size_t)N * IN_DIM / 4) + 255) / 256, 256, 0, st>>>(
        proj, out, meanp, rstdp, g3, be3, N, IN_DIM, 0);
}

// round 7
// speedup vs baseline: 1.7286x; 1.2466x over previous
#include <cuda_runtime.h>
#include <cuda_bf16.h>
#include <math.h>

// Problem constants (shapes fixed by the dataset).
#define NN      50000
#define EEDGES  800000
#define IN_DIM  128
#define H1N     4
#define C1N     64
#define D1      (H1N * C1N)          // 256
#define D2      64
#define EPS_BN  1e-5f
#define NEG_SLOPE 0.2f
#define NEG_BIG  (-1e30f)

// -------------------- scratch (static __device__, no allocs) ----------------
__device__ float    g_h1  [NN * D1];       // x@W1, then BN1/ELU output (layer2 input)
__device__ float    g_o1  [NN * D1];       // GAT1 aggregation output
__device__ float    g_as1 [NN * H1N];
__device__ float    g_ad1 [NN * H1N];
__device__ float    g_h2  [NN * D2];
__device__ float    g_o2  [NN * D2];
__device__ float    g_as2 [NN];
__device__ float    g_ad2 [NN];
__device__ float    g_proj[NN * IN_DIM];
__device__ int      g_deg [NN];
__device__ int      g_rowptr[NN + 1];
__device__ int      g_cursor[NN];
__device__ int      g_srcs[EEDGES];
__device__ double   g_sum [256];
__device__ double   g_sq  [256];
__device__ float    g_mean[256];
__device__ float    g_rstd[256];

__device__ __forceinline__ float lrelu(float v) {
    return v > 0.f ? v : NEG_SLOPE * v;
}

// -------------------- GEMM: C[M,Nc] = A[M,K] @ B[K,Nc] ----------------------
// BM=128, BN=64, BK=16, 256 threads, 8x4 per thread, LDS.128 inner loop.
#define BM 128
#define BN 64
#define BKK 16
#define APAD 132    // row stride of As in floats (16B-aligned: 132*4=528)
__global__ __launch_bounds__(256) void gemm_kernel(
    const float* __restrict__ A, const float* __restrict__ B,
    float* __restrict__ C, int M, int Nc, int K)
{
    __shared__ float As[BKK][APAD];    // As[k][m]
    __shared__ float Bs[BKK][BN];      // Bs[k][n]
    int tid = threadIdx.x;
    int tx = tid & 15;                 // 16 col groups of 4
    int ty = tid >> 4;                 // 16 row groups of 8
    int row0 = blockIdx.y * BM, col0 = blockIdx.x * BN;
    float acc[8][4] = {};

    for (int k0 = 0; k0 < K; k0 += BKK) {
        {   // A tile: 128 rows x 16 k. Each thread: one row, 8 k (2 float4).
            int r  = tid >> 1;
            int c8 = (tid & 1) * 8;
            float4 v0 = make_float4(0, 0, 0, 0), v1 = v0;
            if (row0 + r < M) {
                const float* ap = A + (size_t)(row0 + r) * K + k0 + c8;
                v0 = *(const float4*)ap;
                v1 = *(const float4*)(ap + 4);
            }
            As[c8 + 0][r] = v0.x; As[c8 + 1][r] = v0.y;
            As[c8 + 2][r] = v0.z; As[c8 + 3][r] = v0.w;
            As[c8 + 4][r] = v1.x; As[c8 + 5][r] = v1.y;
            As[c8 + 6][r] = v1.z; As[c8 + 7][r] = v1.w;
        }
        {   // B tile: 16 k x 64 cols. Each thread one float4.
            int r  = tid >> 4;
            int c4 = (tid & 15) * 4;
            *(float4*)&Bs[r][c4] =
                *(const float4*)(B + (size_t)(k0 + r) * Nc + col0 + c4);
        }
        __syncthreads();
        #pragma unroll
        for (int kk = 0; kk < BKK; kk++) {
            float4 a0 = *(const float4*)&As[kk][ty * 8];
            float4 a1 = *(const float4*)&As[kk][ty * 8 + 4];
            float4 b  = *(const float4*)&Bs[kk][tx * 4];
            float av[8] = {a0.x, a0.y, a0.z, a0.w, a1.x, a1.y, a1.z, a1.w};
            float bv[4] = {b.x, b.y, b.z, b.w};
            #pragma unroll
            for (int i = 0; i < 8; i++)
                #pragma unroll
                for (int j = 0; j < 4; j++) acc[i][j] += av[i] * bv[j];
        }
        __syncthreads();
    }
    #pragma unroll
    for (int i = 0; i < 8; i++) {
        int r = row0 + ty * 8 + i;
        if (r < M) {
            float4 v = make_float4(acc[i][0], acc[i][1], acc[i][2], acc[i][3]);
            *(float4*)(C + (size_t)r * Nc + col0 + tx * 4) = v;
        }
    }
}

// -------------------- attention coefficients: [N,H] dot over C --------------
__global__ void alpha_kernel(const float* __restrict__ h,
                             const float* __restrict__ asrc,
                             const float* __restrict__ adst,
                             float* __restrict__ out_s, float* __restrict__ out_d,
                             int N, int H, int C)
{
    int w = (blockIdx.x * blockDim.x + threadIdx.x) >> 5;
    int lane = threadIdx.x & 31;
    if (w >= N * H) return;
    int n = w / H, hh = w - n * H;
    const float* hp = h + (size_t)n * H * C + hh * C;
    float s = 0.f, d = 0.f;
    for (int c = lane; c < C; c += 32) {
        float v = hp[c];
        s += v * asrc[hh * C + c];
        d += v * adst[hh * C + c];
    }
    #pragma unroll
    for (int o = 16; o; o >>= 1) {
        s += __shfl_down_sync(0xffffffffu, s, o);
        d += __shfl_down_sync(0xffffffffu, d, o);
    }
    if (lane == 0) { out_s[w] = s; out_d[w] = d; }
}

// -------------------- CSR build (dst-sorted incoming edge lists) ------------
__global__ void degree_kernel(const int* __restrict__ ei, int* __restrict__ deg, int E)
{
    int e = blockIdx.x * blockDim.x + threadIdx.x;
    if (e < E) atomicAdd(&deg[ei[E + e]], 1);
}

__global__ __launch_bounds__(1024) void scan_kernel(
    const int* __restrict__ deg, int* __restrict__ rowptr,
    int* __restrict__ cursor, int N)
{
    __shared__ int part[1024];
    int tid = threadIdx.x;
    int chunk = (N + 1023) / 1024;
    int b = tid * chunk, e = min(b + chunk, N);
    int s = 0;
    for (int i = b; i < e; i++) s += deg[i];
    part[tid] = s;
    __syncthreads();
    for (int o = 1; o < 1024; o <<= 1) {
        int v = (tid >= o) ? part[tid - o] : 0;
        __syncthreads();
        part[tid] += v;
        __syncthreads();
    }
    int run = tid ? part[tid - 1] : 0;
    for (int i = b; i < e; i++) {
        rowptr[i] = run; cursor[i] = run;
        run += deg[i];
    }
    if (tid == 1023) rowptr[N] = part[1023];
}

__global__ void fill_kernel(const int* __restrict__ ei, int* __restrict__ cursor,
                            int* __restrict__ srcs, int E)
{
    int e = blockIdx.x * blockDim.x + threadIdx.x;
    if (e >= E) return;
    int d = ei[E + e];
    int p = atomicAdd(&cursor[d], 1);
    srcs[p] = ei[e];
}

// ---------- layer-1 GAT aggregation: one warp per node, H=4, C=64 ----------
// Pass 1: 4 online softmaxes (per head) over edges, lane-strided.
// Pass 2: each lane owns 8 contiguous channels (lane>>3 = its head); per edge
// 2x LDG.128 of h[src] + scalar alpha.
__global__ void gat_agg4_kernel(const int* __restrict__ srcs,
                                const int* __restrict__ rowptr,
                                const float* __restrict__ as_,
                                const float* __restrict__ ad_,
                                const float* __restrict__ h,
                                float* __restrict__ out, int N)
{
    int n = (blockIdx.x * blockDim.x + threadIdx.x) >> 5;
    int lane = threadIdx.x & 31;
    if (n >= N) return;
    int beg = rowptr[n], end = rowptr[n + 1];

    float4 ad4 = *(const float4*)(ad_ + n * 4);
    float4 asS = *(const float4*)(as_ + n * 4);

    float m0 = NEG_BIG, m1 = NEG_BIG, m2 = NEG_BIG, m3 = NEG_BIG;
    float s0 = 0.f, s1 = 0.f, s2 = 0.f, s3 = 0.f;
    if (lane == 0) {    // self loop
        m0 = lrelu(asS.x + ad4.x); s0 = 1.f;
        m1 = lrelu(asS.y + ad4.y); s1 = 1.f;
        m2 = lrelu(asS.z + ad4.z); s2 = 1.f;
        m3 = lrelu(asS.w + ad4.w); s3 = 1.f;
    }
    for (int e = beg + lane; e < end; e += 32) {
        float4 a4 = *(const float4*)(as_ + srcs[e] * 4);
        float v;
        v = lrelu(a4.x + ad4.x);
        if (v > m0) { s0 = s0 * __expf(m0 - v) + 1.f; m0 = v; } else s0 += __expf(v - m0);
        v = lrelu(a4.y + ad4.y);
        if (v > m1) { s1 = s1 * __expf(m1 - v) + 1.f; m1 = v; } else s1 += __expf(v - m1);
        v = lrelu(a4.z + ad4.z);
        if (v > m2) { s2 = s2 * __expf(m2 - v) + 1.f; m2 = v; } else s2 += __expf(v - m2);
        v = lrelu(a4.w + ad4.w);
        if (v > m3) { s3 = s3 * __expf(m3 - v) + 1.f; m3 = v; } else s3 += __expf(v - m3);
    }
    #pragma unroll
    for (int o = 16; o; o >>= 1) {
        float mm, ss, mn;
        mm = __shfl_xor_sync(0xffffffffu, m0, o); ss = __shfl_xor_sync(0xffffffffu, s0, o);
        mn = fmaxf(m0, mm); s0 = s0 * __expf(m0 - mn) + ss * __expf(mm - mn); m0 = mn;
        mm = __shfl_xor_sync(0xffffffffu, m1, o); ss = __shfl_xor_sync(0xffffffffu, s1, o);
        mn = fmaxf(m1, mm); s1 = s1 * __expf(m1 - mn) + ss * __expf(mm - mn); m1 = mn;
        mm = __shfl_xor_sync(0xffffffffu, m2, o); ss = __shfl_xor_sync(0xffffffffu, s2, o);
        mn = fmaxf(m2, mm); s2 = s2 * __expf(m2 - mn) + ss * __expf(mm - mn); m2 = mn;
        mm = __shfl_xor_sync(0xffffffffu, m3, o); ss = __shfl_xor_sync(0xffffffffu, s3, o);
        mn = fmaxf(m3, mm); s3 = s3 * __expf(m3 - mn) + ss * __expf(mm - mn); m3 = mn;
    }

    int hd = lane >> 3;                          // this lane's head
    float mh  = (hd == 0) ? m0 : (hd == 1) ? m1 : (hd == 2) ? m2 : m3;
    float sh  = (hd == 0) ? s0 : (hd == 1) ? s1 : (hd == 2) ? s2 : s3;
    float adh = (hd == 0) ? ad4.x : (hd == 1) ? ad4.y : (hd == 2) ? ad4.z : ad4.w;
    float inv = 1.f / (sh + 1e-16f);

    float4 acc0 = make_float4(0, 0, 0, 0), acc1 = acc0;
    for (int e = beg; e < end; e++) {
        int s = srcs[e];
        float v = lrelu(as_[s * 4 + hd] + adh);
        float a = __expf(v - mh) * inv;
        const float4* hp = (const float4*)(h + (size_t)s * 256 + lane * 8);
        float4 v0 = hp[0], v1 = hp[1];
        acc0.x += a * v0.x; acc0.y += a * v0.y; acc0.z += a * v0.z; acc0.w += a * v0.w;
        acc1.x += a * v1.x; acc1.y += a * v1.y; acc1.z += a * v1.z; acc1.w += a * v1.w;
    }
    {   // self loop
        float v = lrelu(as_[n * 4 + hd] + adh);
        float a = __expf(v - mh) * inv;
        const float4* hp = (const float4*)(h + (size_t)n * 256 + lane * 8);
        float4 v0 = hp[0], v1 = hp[1];
        acc0.x += a * v0.x; acc0.y += a * v0.y; acc0.z += a * v0.z; acc0.w += a * v0.w;
        acc1.x += a * v1.x; acc1.y += a * v1.y; acc1.z += a * v1.z; acc1.w += a * v1.w;
    }
    float4* op = (float4*)(out + (size_t)n * 256 + lane * 8);
    op[0] = acc0; op[1] = acc1;
}

// ---------- layer-2 GAT aggregation: warp per node, H=1, C=64 ---------------
__global__ void gat_agg1_kernel(const int* __restrict__ srcs,
                                const int* __restrict__ rowptr,
                                const float* __restrict__ as_,
                                const float* __restrict__ ad_,
                                const float* __restrict__ h,
                                float* __restrict__ out, int N)
{
    int n = (blockIdx.x * blockDim.x + threadIdx.x) >> 5;
    int lane = threadIdx.x & 31;
    if (n >= N) return;
    int beg = rowptr[n], end = rowptr[n + 1];
    float ad = ad_[n];
    float as_self = as_[n];

    float m = NEG_BIG, ssum = 0.f;
    if (lane == 0) {
        m = lrelu(as_self + ad); ssum = 1.f;
    }
    for (int e = beg + lane; e < end; e += 32) {
        float v = lrelu(as_[srcs[e]] + ad);
        if (v > m) { ssum = ssum * __expf(m - v) + 1.f; m = v; } else ssum += __expf(v - m);
    }
    #pragma unroll
    for (int o = 16; o; o >>= 1) {
        float m2 = __shfl_xor_sync(0xffffffffu, m, o);
        float s2 = __shfl_xor_sync(0xffffffffu, ssum, o);
        float mn = fmaxf(m, m2);
        ssum = ssum * __expf(m - mn) + s2 * __expf(m2 - mn);
        m = mn;
    }
    float inv = 1.f / (ssum + 1e-16f);

    float acc0 = 0.f, acc1 = 0.f;
    for (int e = beg; e < end; e++) {
        int s = srcs[e];
        float v = lrelu(as_[s] + ad);
        float a = __expf(v - m) * inv;
        const float* hp = h + (size_t)s * 64;
        acc0 += a * hp[lane];
        acc1 += a * hp[lane + 32];
    }
    {   // self loop
        float v = lrelu(as_self + ad);
        float a = __expf(v - m) * inv;
        const float* hp = h + (size_t)n * 64;
        acc0 += a * hp[lane];
        acc1 += a * hp[lane + 32];
    }
    float* op = out + (size_t)n * 64;
    op[lane]      = acc0;
    op[lane + 32] = acc1;
}

// -------------------- batchnorm stats (fp32 partials, fp64 combine) ---------
__global__ void bn_stats_kernel(const float* __restrict__ x,
                                double* __restrict__ sum, double* __restrict__ sq,
                                int N, int C)
{
    int c = threadIdx.x;        // blockDim.x == C
    float s = 0.f, q = 0.f;
    for (int r = blockIdx.x; r < N; r += gridDim.x) {
        float v = x[(size_t)r * C + c];
        s += v; q += v * v;
    }
    atomicAdd(&sum[c], (double)s);
    atomicAdd(&sq[c], (double)q);
}

__global__ void bn_final_kernel(const double* __restrict__ sum, const double* __restrict__ sq,
                                float* __restrict__ mean, float* __restrict__ rstd,
                                int N, int C)
{
    int c = blockIdx.x * blockDim.x + threadIdx.x;
    if (c >= C) return;
    double mu = sum[c] / N;
    double var = sq[c] / N - mu * mu;
    mean[c] = (float)mu;
    rstd[c] = (float)(1.0 / sqrt(var + (double)EPS_BN));
}

__global__ void bn_apply_kernel(const float* __restrict__ x, float* __restrict__ y,
                                const float* __restrict__ mean, const float* __restrict__ rstd,
                                const float* __restrict__ g, const float* __restrict__ be,
                                int N, int C, int do_elu)
{
    int i4 = blockIdx.x * blockDim.x + threadIdx.x;      // float4 index
    size_t total4 = ((size_t)N * C) >> 2;
    if ((size_t)i4 >= total4) return;
    int c0 = (i4 << 2) % C;
    float4 v = ((const float4*)x)[i4];
    float r[4] = {v.x, v.y, v.z, v.w};
    #pragma unroll
    for (int j = 0; j < 4; j++) {
        int c = c0 + j;
        float t = (r[j] - mean[c]) * rstd[c] * g[c] + be[c];
        if (do_elu) t = t > 0.f ? t : __expf(t) - 1.f;
        r[j] = t;
    }
    ((float4*)y)[i4] = make_float4(r[0], r[1], r[2], r[3]);
}

// -------------------- launch -----------------------------------------------
extern "C" void kernel_launch(void* const* d_in, const int* in_sizes, int n_in,
                              void* d_out, int out_size)
{
    const float* x   = (const float*)d_in[0];
    const int*   ei  = (const int*)  d_in[1];
    const float* W1  = (const float*)d_in[2];
    const float* a1s = (const float*)d_in[3];
    const float* a1d = (const float*)d_in[4];
    // d_in[5] = b1 : followed by BN -> channel-shift invariant -> skipped
    const float* W2  = (const float*)d_in[6];
    const float* a2s = (const float*)d_in[7];
    const float* a2d = (const float*)d_in[8];
    // d_in[9] = b2 : skipped (BN invariance)
    const float* Wp  = (const float*)d_in[10];
    // d_in[11] = bp : skipped (BN invariance)
    const float* g1  = (const float*)d_in[12];
    const float* be1 = (const float*)d_in[13];
    const float* g2  = (const float*)d_in[14];
    const float* be2 = (const float*)d_in[15];
    const float* g3  = (const float*)d_in[16];
    const float* be3 = (const float*)d_in[17];
    float* out = (float*)d_out;

    const int N = in_sizes[0] / IN_DIM;       // 50000
    const int E = in_sizes[1] / 2;            // 800000

    float *h1, *o1, *as1, *ad1;
    float *h2, *o2, *as2, *ad2, *proj, *meanp, *rstdp;
    int *deg, *rowptr, *cursor, *srcs;
    double *sump, *sqp;
    cudaGetSymbolAddress((void**)&h1,   g_h1);
    cudaGetSymbolAddress((void**)&o1,   g_o1);
    cudaGetSymbolAddress((void**)&as1,  g_as1);
    cudaGetSymbolAddress((void**)&ad1,  g_ad1);
    cudaGetSymbolAddress((void**)&h2,   g_h2);
    cudaGetSymbolAddress((void**)&o2,   g_o2);
    cudaGetSymbolAddress((void**)&as2,  g_as2);
    cudaGetSymbolAddress((void**)&ad2,  g_ad2);
    cudaGetSymbolAddress((void**)&proj, g_proj);
    cudaGetSymbolAddress((void**)&deg,    g_deg);
    cudaGetSymbolAddress((void**)&rowptr, g_rowptr);
    cudaGetSymbolAddress((void**)&cursor, g_cursor);
    cudaGetSymbolAddress((void**)&srcs,   g_srcs);
    cudaGetSymbolAddress((void**)&sump, g_sum);
    cudaGetSymbolAddress((void**)&sqp,  g_sq);
    cudaGetSymbolAddress((void**)&meanp, g_mean);
    cudaGetSymbolAddress((void**)&rstdp, g_rstd);

    cudaStream_t st = 0;

    // ---------------- CSR build (shared by both layers) ---------------------
    cudaMemsetAsync(deg, 0, (size_t)N * sizeof(int), st);
    degree_kernel<<<(E + 255) / 256, 256, 0, st>>>(ei, deg, E);
    scan_kernel<<<1, 1024, 0, st>>>(deg, rowptr, cursor, N);
    fill_kernel<<<(E + 255) / 256, 256, 0, st>>>(ei, cursor, srcs, E);

    // ---------------- layer 1: GATConv(128 -> 4x64, concat) ----------------
    {
        dim3 grid(D1 / BN, (N + BM - 1) / BM);
        gemm_kernel<<<grid, 256, 0, st>>>(x, W1, h1, N, D1, IN_DIM);
    }
    alpha_kernel<<<(N * H1N * 32 + 255) / 256, 256, 0, st>>>(h1, a1s, a1d, as1, ad1, N, H1N, C1N);
    gat_agg4_kernel<<<(N * 32 + 255) / 256, 256, 0, st>>>(
        srcs, rowptr, as1, ad1, h1, o1, N);

    // BN1 + ELU -> h1 (reused as layer-2 input)
    cudaMemsetAsync(sump, 0, D1 * sizeof(double), st);
    cudaMemsetAsync(sqp,  0, D1 * sizeof(double), st);
    bn_stats_kernel<<<512, D1, 0, st>>>(o1, sump, sqp, N, D1);
    bn_final_kernel<<<1, D1, 0, st>>>(sump, sqp, meanp, rstdp, N, D1);
    bn_apply_kernel<<<(((size_t)N * D1 / 4) + 255) / 256, 256, 0, st>>>(
        o1, h1, meanp, rstdp, g1, be1, N, D1, 1);

    // ---------------- layer 2: GATConv(256 -> 64, H=1) ---------------------
    {
        dim3 grid(D2 / BN, (N + BM - 1) / BM);
        gemm_kernel<<<grid, 256, 0, st>>>(h1, W2, h2, N, D2, D1);
    }
    alpha_kernel<<<(N * 32 + 255) / 256, 256, 0, st>>>(h2, a2s, a2d, as2, ad2, N, 1, D2);
    gat_agg1_kernel<<<(N * 32 + 255) / 256, 256, 0, st>>>(
        srcs, rowptr, as2, ad2, h2, o2, N);

    // BN2 + ELU -> h2 (reused as projection input)
    cudaMemsetAsync(sump, 0, D2 * sizeof(double), st);
    cudaMemsetAsync(sqp,  0, D2 * sizeof(double), st);
    bn_stats_kernel<<<512, D2, 0, st>>>(o2, sump, sqp, N, D2);
    bn_final_kernel<<<1, D2, 0, st>>>(sump, sqp, meanp, rstdp, N, D2);
    bn_apply_kernel<<<(((size_t)N * D2 / 4) + 255) / 256, 256, 0, st>>>(
        o2, h2, meanp, rstdp, g2, be2, N, D2, 1);

    // ---------------- projection 64 -> 128 + BN3 ---------------------------
    {
        dim3 grid(IN_DIM / BN, (N + BM - 1) / BM);
        gemm_kernel<<<grid, 256, 0, st>>>(h2, Wp, proj, N, IN_DIM, D2);
    }
    cudaMemsetAsync(sump, 0, IN_DIM * sizeof(double), st);
    cudaMemsetAsync(sqp,  0, IN_DIM * sizeof(double), st);
    bn_stats_kernel<<<512, IN_DIM, 0, st>>>(proj, sump, sqp, N, IN_DIM);
    bn_final_kernel<<<1, IN_DIM, 0, st>>>(sump, sqp, meanp, rstdp, N, IN_DIM);
    bn_apply_kernel<<<(((size_t)N * IN_DIM / 4) + 255) / 256, 256, 0, st>>>(
        proj, out, meanp, rstdp, g3, be3, N, IN_DIM, 0);
}

// round 9
// speedup vs baseline: 2.8018x; 1.6209x over previous
#include <cuda_runtime.h>
#include <cuda_bf16.h>
#include <mma.h>
#include <math.h>

using namespace nvcuda;

// Problem constants (shapes fixed by the dataset).
#define NN      50000
#define EEDGES  800000
#define IN_DIM  128
#define H1N     4
#define C1N     64
#define D1      (H1N * C1N)          // 256
#define D2      64
#define EPS_BN  1e-5f
#define NEG_SLOPE 0.2f
#define NEG_BIG  (-1e30f)

// -------------------- scratch (static __device__, no allocs) ----------------
__device__ float    g_h1  [NN * D1];       // x@W1, then BN1/ELU output (layer2 input)
__device__ float    g_o1  [NN * D1];       // GAT1 aggregation output
__device__ float    g_as1 [NN * H1N];
__device__ float    g_ad1 [NN * H1N];
__device__ float    g_h2  [NN * D2];
__device__ float    g_o2  [NN * D2];
__device__ float    g_as2 [NN];
__device__ float    g_ad2 [NN];
__device__ float    g_proj[NN * IN_DIM];
__device__ int      g_deg [NN];
__device__ int      g_rowptr[NN + 1];
__device__ int      g_cursor[NN];
__device__ int      g_srcs[EEDGES];
__device__ double   g_sum [256];
__device__ double   g_sq  [256];
__device__ float    g_mean[256];
__device__ float    g_rstd[256];

__device__ __forceinline__ float lrelu(float v) {
    return v > 0.f ? v : NEG_SLOPE * v;
}

// ------------- GEMM (TF32 tensor cores): C[M,Nc] = A[M,K] @ B[K,Nc] ---------
// BM=128, BN=64, BK=16. 256 threads = 8 warps in 4x2; each warp 32x32 output
// via 2x2 wmma m16n16k8 accumulators. A,B staged in smem as tf32.
#define GBM 128
#define GBN 64
#define ALD 20      // A smem leading dim (mult of 4)
#define BLD 68      // B smem leading dim (mult of 4)
__global__ __launch_bounds__(256) void gemm_tf32_kernel(
    const float* __restrict__ A, const float* __restrict__ B,
    float* __restrict__ C, int M, int Nc, int K)
{
    __shared__ float As[GBM][ALD];   // 128x16 tile (tf32 values)
    __shared__ float Bs[16][BLD];    // 16x64 tile
    int tid = threadIdx.x;
    int wid  = tid >> 5;
    int wrow = wid >> 1;             // 0..3 -> 32-row strip
    int wcol = wid & 1;              // 0..1 -> 32-col strip
    int row0 = blockIdx.y * GBM, col0 = blockIdx.x * GBN;

    wmma::fragment<wmma::accumulator, 16, 16, 8, float> acc[2][2];
    #pragma unroll
    for (int i = 0; i < 2; i++)
        #pragma unroll
        for (int j = 0; j < 2; j++) wmma::fill_fragment(acc[i][j], 0.f);

    for (int k0 = 0; k0 < K; k0 += 16) {
        {   // A tile: 128 rows x 16 k. Each thread: one row, 8 k (2 float4).
            int r  = tid >> 1;
            int c8 = (tid & 1) * 8;
            float4 v0 = make_float4(0, 0, 0, 0), v1 = v0;
            if (row0 + r < M) {
                const float* ap = A + (size_t)(row0 + r) * K + k0 + c8;
                v0 = *(const float4*)ap;
                v1 = *(const float4*)(ap + 4);
            }
            As[r][c8 + 0] = wmma::__float_to_tf32(v0.x);
            As[r][c8 + 1] = wmma::__float_to_tf32(v0.y);
            As[r][c8 + 2] = wmma::__float_to_tf32(v0.z);
            As[r][c8 + 3] = wmma::__float_to_tf32(v0.w);
            As[r][c8 + 4] = wmma::__float_to_tf32(v1.x);
            As[r][c8 + 5] = wmma::__float_to_tf32(v1.y);
            As[r][c8 + 6] = wmma::__float_to_tf32(v1.z);
            As[r][c8 + 7] = wmma::__float_to_tf32(v1.w);
        }
        {   // B tile: 16 k x 64 cols. Each thread one float4.
            int r  = tid >> 4;
            int c4 = (tid & 15) * 4;
            float4 v = *(const float4*)(B + (size_t)(k0 + r) * Nc + col0 + c4);
            Bs[r][c4 + 0] = wmma::__float_to_tf32(v.x);
            Bs[r][c4 + 1] = wmma::__float_to_tf32(v.y);
            Bs[r][c4 + 2] = wmma::__float_to_tf32(v.z);
            Bs[r][c4 + 3] = wmma::__float_to_tf32(v.w);
        }
        __syncthreads();
        #pragma unroll
        for (int kk = 0; kk < 16; kk += 8) {
            wmma::fragment<wmma::matrix_a, 16, 16, 8, wmma::precision::tf32, wmma::row_major> af[2];
            wmma::fragment<wmma::matrix_b, 16, 16, 8, wmma::precision::tf32, wmma::row_major> bf[2];
            wmma::load_matrix_sync(af[0], &As[wrow * 32     ][kk], ALD);
            wmma::load_matrix_sync(af[1], &As[wrow * 32 + 16][kk], ALD);
            wmma::load_matrix_sync(bf[0], &Bs[kk][wcol * 32     ], BLD);
            wmma::load_matrix_sync(bf[1], &Bs[kk][wcol * 32 + 16], BLD);
            #pragma unroll
            for (int i = 0; i < 2; i++)
                #pragma unroll
                for (int j = 0; j < 2; j++)
                    wmma::mma_sync(acc[i][j], af[i], bf[j], acc[i][j]);
        }
        __syncthreads();
    }

    // Store. M may not be a multiple of 16 in general: stage partial tiles.
    __syncthreads();                   // As no longer needed; reuse as staging
    float* stage = &As[0][0] + wid * 256;   // 16x16 per warp
    int lane = tid & 31;
    #pragma unroll
    for (int i = 0; i < 2; i++) {
        int r = row0 + wrow * 32 + i * 16;
        #pragma unroll
        for (int j = 0; j < 2; j++) {
            int c = col0 + wcol * 32 + j * 16;
            if (r + 16 <= M) {
                wmma::store_matrix_sync(C + (size_t)r * Nc + c, acc[i][j], Nc,
                                        wmma::mem_row_major);
            } else if (r < M) {
                wmma::store_matrix_sync(stage, acc[i][j], 16, wmma::mem_row_major);
                __syncwarp();
                for (int t = lane; t < 256; t += 32) {
                    int rr = t >> 4, cc = t & 15;
                    if (r + rr < M)
                        C[(size_t)(r + rr) * Nc + c + cc] = stage[t];
                }
                __syncwarp();
            }
        }
    }
}

// -------------------- attention coefficients: [N,H] dot over C --------------
__global__ void alpha_kernel(const float* __restrict__ h,
                             const float* __restrict__ asrc,
                             const float* __restrict__ adst,
                             float* __restrict__ out_s, float* __restrict__ out_d,
                             int N, int H, int C)
{
    int w = (blockIdx.x * blockDim.x + threadIdx.x) >> 5;
    int lane = threadIdx.x & 31;
    if (w >= N * H) return;
    int n = w / H, hh = w - n * H;
    const float* hp = h + (size_t)n * H * C + hh * C;
    float s = 0.f, d = 0.f;
    for (int c = lane; c < C; c += 32) {
        float v = hp[c];
        s += v * asrc[hh * C + c];
        d += v * adst[hh * C + c];
    }
    #pragma unroll
    for (int o = 16; o; o >>= 1) {
        s += __shfl_down_sync(0xffffffffu, s, o);
        d += __shfl_down_sync(0xffffffffu, d, o);
    }
    if (lane == 0) { out_s[w] = s; out_d[w] = d; }
}

// -------------------- CSR build (dst-sorted incoming edge lists) ------------
__global__ void degree_kernel(const int* __restrict__ ei, int* __restrict__ deg, int E)
{
    int e = blockIdx.x * blockDim.x + threadIdx.x;
    if (e < E) atomicAdd(&deg[ei[E + e]], 1);
}

__global__ __launch_bounds__(1024) void scan_kernel(
    const int* __restrict__ deg, int* __restrict__ rowptr,
    int* __restrict__ cursor, int N)
{
    __shared__ int part[1024];
    int tid = threadIdx.x;
    int chunk = (N + 1023) / 1024;
    int b = tid * chunk, e = min(b + chunk, N);
    int s = 0;
    for (int i = b; i < e; i++) s += deg[i];
    part[tid] = s;
    __syncthreads();
    for (int o = 1; o < 1024; o <<= 1) {
        int v = (tid >= o) ? part[tid - o] : 0;
        __syncthreads();
        part[tid] += v;
        __syncthreads();
    }
    int run = tid ? part[tid - 1] : 0;
    for (int i = b; i < e; i++) {
        rowptr[i] = run; cursor[i] = run;
        run += deg[i];
    }
    if (tid == 1023) rowptr[N] = part[1023];
}

__global__ void fill_kernel(const int* __restrict__ ei, int* __restrict__ cursor,
                            int* __restrict__ srcs, int E)
{
    int e = blockIdx.x * blockDim.x + threadIdx.x;
    if (e >= E) return;
    int d = ei[E + e];
    int p = atomicAdd(&cursor[d], 1);
    srcs[p] = ei[e];
}

// ---------- layer-1 GAT aggregation: one warp per node, H=4, C=64 ----------
__global__ void gat_agg4_kernel(const int* __restrict__ srcs,
                                const int* __restrict__ rowptr,
                                const float* __restrict__ as_,
                                const float* __restrict__ ad_,
                                const float* __restrict__ h,
                                float* __restrict__ out, int N)
{
    int n = (blockIdx.x * blockDim.x + threadIdx.x) >> 5;
    int lane = threadIdx.x & 31;
    if (n >= N) return;
    int beg = rowptr[n], end = rowptr[n + 1];

    float4 ad4 = *(const float4*)(ad_ + n * 4);
    float4 asS = *(const float4*)(as_ + n * 4);

    float m0 = NEG_BIG, m1 = NEG_BIG, m2 = NEG_BIG, m3 = NEG_BIG;
    float s0 = 0.f, s1 = 0.f, s2 = 0.f, s3 = 0.f;
    if (lane == 0) {    // self loop
        m0 = lrelu(asS.x + ad4.x); s0 = 1.f;
        m1 = lrelu(asS.y + ad4.y); s1 = 1.f;
        m2 = lrelu(asS.z + ad4.z); s2 = 1.f;
        m3 = lrelu(asS.w + ad4.w); s3 = 1.f;
    }
    for (int e = beg + lane; e < end; e += 32) {
        float4 a4 = *(const float4*)(as_ + srcs[e] * 4);
        float v;
        v = lrelu(a4.x + ad4.x);
        if (v > m0) { s0 = s0 * __expf(m0 - v) + 1.f; m0 = v; } else s0 += __expf(v - m0);
        v = lrelu(a4.y + ad4.y);
        if (v > m1) { s1 = s1 * __expf(m1 - v) + 1.f; m1 = v; } else s1 += __expf(v - m1);
        v = lrelu(a4.z + ad4.z);
        if (v > m2) { s2 = s2 * __expf(m2 - v) + 1.f; m2 = v; } else s2 += __expf(v - m2);
        v = lrelu(a4.w + ad4.w);
        if (v > m3) { s3 = s3 * __expf(m3 - v) + 1.f; m3 = v; } else s3 += __expf(v - m3);
    }
    #pragma unroll
    for (int o = 16; o; o >>= 1) {
        float mm, ss, mn;
        mm = __shfl_xor_sync(0xffffffffu, m0, o); ss = __shfl_xor_sync(0xffffffffu, s0, o);
        mn = fmaxf(m0, mm); s0 = s0 * __expf(m0 - mn) + ss * __expf(mm - mn); m0 = mn;
        mm = __shfl_xor_sync(0xffffffffu, m1, o); ss = __shfl_xor_sync(0xffffffffu, s1, o);
        mn = fmaxf(m1, mm); s1 = s1 * __expf(m1 - mn) + ss * __expf(mm - mn); m1 = mn;
        mm = __shfl_xor_sync(0xffffffffu, m2, o); ss = __shfl_xor_sync(0xffffffffu, s2, o);
        mn = fmaxf(m2, mm); s2 = s2 * __expf(m2 - mn) + ss * __expf(mm - mn); m2 = mn;
        mm = __shfl_xor_sync(0xffffffffu, m3, o); ss = __shfl_xor_sync(0xffffffffu, s3, o);
        mn = fmaxf(m3, mm); s3 = s3 * __expf(m3 - mn) + ss * __expf(mm - mn); m3 = mn;
    }

    int hd = lane >> 3;                          // this lane's head
    float mh  = (hd == 0) ? m0 : (hd == 1) ? m1 : (hd == 2) ? m2 : m3;
    float sh  = (hd == 0) ? s0 : (hd == 1) ? s1 : (hd == 2) ? s2 : s3;
    float adh = (hd == 0) ? ad4.x : (hd == 1) ? ad4.y : (hd == 2) ? ad4.z : ad4.w;
    float inv = 1.f / (sh + 1e-16f);

    float4 acc0 = make_float4(0, 0, 0, 0), acc1 = acc0;
    for (int e = beg; e < end; e++) {
        int s = srcs[e];
        float v = lrelu(as_[s * 4 + hd] + adh);
        float a = __expf(v - mh) * inv;
        const float4* hp = (const float4*)(h + (size_t)s * 256 + lane * 8);
        float4 v0 = hp[0], v1 = hp[1];
        acc0.x += a * v0.x; acc0.y += a * v0.y; acc0.z += a * v0.z; acc0.w += a * v0.w;
        acc1.x += a * v1.x; acc1.y += a * v1.y; acc1.z += a * v1.z; acc1.w += a * v1.w;
    }
    {   // self loop
        float v = lrelu(as_[n * 4 + hd] + adh);
        float a = __expf(v - mh) * inv;
        const float4* hp = (const float4*)(h + (size_t)n * 256 + lane * 8);
        float4 v0 = hp[0], v1 = hp[1];
        acc0.x += a * v0.x; acc0.y += a * v0.y; acc0.z += a * v0.z; acc0.w += a * v0.w;
        acc1.x += a * v1.x; acc1.y += a * v1.y; acc1.z += a * v1.z; acc1.w += a * v1.w;
    }
    float4* op = (float4*)(out + (size_t)n * 256 + lane * 8);
    op[0] = acc0; op[1] = acc1;
}

// ---------- layer-2 GAT aggregation: warp per node, H=1, C=64 ---------------
__global__ void gat_agg1_kernel(const int* __restrict__ srcs,
                                const int* __restrict__ rowptr,
                                const float* __restrict__ as_,
                                const float* __restrict__ ad_,
                                const float* __restrict__ h,
                                float* __restrict__ out, int N)
{
    int n = (blockIdx.x * blockDim.x + threadIdx.x) >> 5;
    int lane = threadIdx.x & 31;
    if (n >= N) return;
    int beg = rowptr[n], end = rowptr[n + 1];
    float ad = ad_[n];
    float as_self = as_[n];

    float m = NEG_BIG, ssum = 0.f;
    if (lane == 0) {
        m = lrelu(as_self + ad); ssum = 1.f;
    }
    for (int e = beg + lane; e < end; e += 32) {
        float v = lrelu(as_[srcs[e]] + ad);
        if (v > m) { ssum = ssum * __expf(m - v) + 1.f; m = v; } else ssum += __expf(v - m);
    }
    #pragma unroll
    for (int o = 16; o; o >>= 1) {
        float m2 = __shfl_xor_sync(0xffffffffu, m, o);
        float s2 = __shfl_xor_sync(0xffffffffu, ssum, o);
        float mn = fmaxf(m, m2);
        ssum = ssum * __expf(m - mn) + s2 * __expf(m2 - mn);
        m = mn;
    }
    float inv = 1.f / (ssum + 1e-16f);

    float acc0 = 0.f, acc1 = 0.f;
    for (int e = beg; e < end; e++) {
        int s = srcs[e];
        float v = lrelu(as_[s] + ad);
        float a = __expf(v - m) * inv;
        const float* hp = h + (size_t)s * 64;
        acc0 += a * hp[lane];
        acc1 += a * hp[lane + 32];
    }
    {   // self loop
        float v = lrelu(as_self + ad);
        float a = __expf(v - m) * inv;
        const float* hp = h + (size_t)n * 64;
        acc0 += a * hp[lane];
        acc1 += a * hp[lane + 32];
    }
    float* op = out + (size_t)n * 64;
    op[lane]      = acc0;
    op[lane + 32] = acc1;
}

// -------------------- batchnorm stats (fp32 partials, fp64 combine) ---------
__global__ void bn_stats_kernel(const float* __restrict__ x,
                                double* __restrict__ sum, double* __restrict__ sq,
                                int N, int C)
{
    int c = threadIdx.x;        // blockDim.x == C
    float s = 0.f, q = 0.f;
    for (int r = blockIdx.x; r < N; r += gridDim.x) {
        float v = x[(size_t)r * C + c];
        s += v; q += v * v;
    }
    atomicAdd(&sum[c], (double)s);
    atomicAdd(&sq[c], (double)q);
}

__global__ void bn_final_kernel(const double* __restrict__ sum, const double* __restrict__ sq,
                                float* __restrict__ mean, float* __restrict__ rstd,
                                int N, int C)
{
    int c = blockIdx.x * blockDim.x + threadIdx.x;
    if (c >= C) return;
    double mu = sum[c] / N;
    double var = sq[c] / N - mu * mu;
    mean[c] = (float)mu;
    rstd[c] = (float)(1.0 / sqrt(var + (double)EPS_BN));
}

__global__ void bn_apply_kernel(const float* __restrict__ x, float* __restrict__ y,
                                const float* __restrict__ mean, const float* __restrict__ rstd,
                                const float* __restrict__ g, const float* __restrict__ be,
                                int N, int C, int do_elu)
{
    int i4 = blockIdx.x * blockDim.x + threadIdx.x;      // float4 index
    size_t total4 = ((size_t)N * C) >> 2;
    if ((size_t)i4 >= total4) return;
    int c0 = (i4 << 2) % C;
    float4 v = ((const float4*)x)[i4];
    float r[4] = {v.x, v.y, v.z, v.w};
    #pragma unroll
    for (int j = 0; j < 4; j++) {
        int c = c0 + j;
        float t = (r[j] - mean[c]) * rstd[c] * g[c] + be[c];
        if (do_elu) t = t > 0.f ? t : __expf(t) - 1.f;
        r[j] = t;
    }
    ((float4*)y)[i4] = make_float4(r[0], r[1], r[2], r[3]);
}

// -------------------- launch -----------------------------------------------
extern "C" void kernel_launch(void* const* d_in, const int* in_sizes, int n_in,
                              void* d_out, int out_size)
{
    const float* x   = (const float*)d_in[0];
    const int*   ei  = (const int*)  d_in[1];
    const float* W1  = (const float*)d_in[2];
    const float* a1s = (const float*)d_in[3];
    const float* a1d = (const float*)d_in[4];
    // d_in[5] = b1 : followed by BN -> channel-shift invariant -> skipped
    const float* W2  = (const float*)d_in[6];
    const float* a2s = (const float*)d_in[7];
    const float* a2d = (const float*)d_in[8];
    // d_in[9] = b2 : skipped (BN invariance)
    const float* Wp  = (const float*)d_in[10];
    // d_in[11] = bp : skipped (BN invariance)
    const float* g1  = (const float*)d_in[12];
    const float* be1 = (const float*)d_in[13];
    const float* g2  = (const float*)d_in[14];
    const float* be2 = (const float*)d_in[15];
    const float* g3  = (const float*)d_in[16];
    const float* be3 = (const float*)d_in[17];
    float* out = (float*)d_out;

    const int N = in_sizes[0] / IN_DIM;       // 50000
    const int E = in_sizes[1] / 2;            // 800000

    float *h1, *o1, *as1, *ad1;
    float *h2, *o2, *as2, *ad2, *proj, *meanp, *rstdp;
    int *deg, *rowptr, *cursor, *srcs;
    double *sump, *sqp;
    cudaGetSymbolAddress((void**)&h1,   g_h1);
    cudaGetSymbolAddress((void**)&o1,   g_o1);
    cudaGetSymbolAddress((void**)&as1,  g_as1);
    cudaGetSymbolAddress((void**)&ad1,  g_ad1);
    cudaGetSymbolAddress((void**)&h2,   g_h2);
    cudaGetSymbolAddress((void**)&o2,   g_o2);
    cudaGetSymbolAddress((void**)&as2,  g_as2);
    cudaGetSymbolAddress((void**)&ad2,  g_ad2);
    cudaGetSymbolAddress((void**)&proj, g_proj);
    cudaGetSymbolAddress((void**)&deg,    g_deg);
    cudaGetSymbolAddress((void**)&rowptr, g_rowptr);
    cudaGetSymbolAddress((void**)&cursor, g_cursor);
    cudaGetSymbolAddress((void**)&srcs,   g_srcs);
    cudaGetSymbolAddress((void**)&sump, g_sum);
    cudaGetSymbolAddress((void**)&sqp,  g_sq);
    cudaGetSymbolAddress((void**)&meanp, g_mean);
    cudaGetSymbolAddress((void**)&rstdp, g_rstd);

    cudaStream_t st = 0;

    // ---------------- CSR build (shared by both layers) ---------------------
    cudaMemsetAsync(deg, 0, (size_t)N * sizeof(int), st);
    degree_kernel<<<(E + 255) / 256, 256, 0, st>>>(ei, deg, E);
    scan_kernel<<<1, 1024, 0, st>>>(deg, rowptr, cursor, N);
    fill_kernel<<<(E + 255) / 256, 256, 0, st>>>(ei, cursor, srcs, E);

    // ---------------- layer 1: GATConv(128 -> 4x64, concat) ----------------
    {
        dim3 grid(D1 / GBN, (N + GBM - 1) / GBM);
        gemm_tf32_kernel<<<grid, 256, 0, st>>>(x, W1, h1, N, D1, IN_DIM);
    }
    alpha_kernel<<<(N * H1N * 32 + 255) / 256, 256, 0, st>>>(h1, a1s, a1d, as1, ad1, N, H1N, C1N);
    gat_agg4_kernel<<<(N * 32 + 255) / 256, 256, 0, st>>>(
        srcs, rowptr, as1, ad1, h1, o1, N);

    // BN1 + ELU -> h1 (reused as layer-2 input)
    cudaMemsetAsync(sump, 0, D1 * sizeof(double), st);
    cudaMemsetAsync(sqp,  0, D1 * sizeof(double), st);
    bn_stats_kernel<<<512, D1, 0, st>>>(o1, sump, sqp, N, D1);
    bn_final_kernel<<<1, D1, 0, st>>>(sump, sqp, meanp, rstdp, N, D1);
    bn_apply_kernel<<<(((size_t)N * D1 / 4) + 255) / 256, 256, 0, st>>>(
        o1, h1, meanp, rstdp, g1, be1, N, D1, 1);

    // ---------------- layer 2: GATConv(256 -> 64, H=1) ---------------------
    {
        dim3 grid(D2 / GBN, (N + GBM - 1) / GBM);
        gemm_tf32_kernel<<<grid, 256, 0, st>>>(h1, W2, h2, N, D2, D1);
    }
    alpha_kernel<<<(N * 32 + 255) / 256, 256, 0, st>>>(h2, a2s, a2d, as2, ad2, N, 1, D2);
    gat_agg1_kernel<<<(N * 32 + 255) / 256, 256, 0, st>>>(
        srcs, rowptr, as2, ad2, h2, o2, N);

    // BN2 + ELU -> h2 (reused as projection input)
    cudaMemsetAsync(sump, 0, D2 * sizeof(double), st);
    cudaMemsetAsync(sqp,  0, D2 * sizeof(double), st);
    bn_stats_kernel<<<512, D2, 0, st>>>(o2, sump, sqp, N, D2);
    bn_final_kernel<<<1, D2, 0, st>>>(sump, sqp, meanp, rstdp, N, D2);
    bn_apply_kernel<<<(((size_t)N * D2 / 4) + 255) / 256, 256, 0, st>>>(
        o2, h2, meanp, rstdp, g2, be2, N, D2, 1);

    // ---------------- projection 64 -> 128 + BN3 ---------------------------
    {
        dim3 grid(IN_DIM / GBN, (N + GBM - 1) / GBM);
        gemm_tf32_kernel<<<grid, 256, 0, st>>>(h2, Wp, proj, N, IN_DIM, D2);
    }
    cudaMemsetAsync(sump, 0, IN_DIM * sizeof(double), st);
    cudaMemsetAsync(sqp,  0, IN_DIM * sizeof(double), st);
    bn_stats_kernel<<<512, IN_DIM, 0, st>>>(proj, sump, sqp, N, IN_DIM);
    bn_final_kernel<<<1, IN_DIM, 0, st>>>(sump, sqp, meanp, rstdp, N, IN_DIM);
    bn_apply_kernel<<<(((size_t)N * IN_DIM / 4) + 255) / 256, 256, 0, st>>>(
        proj, out, meanp, rstdp, g3, be3, N, IN_DIM, 0);
}